// round 2
// baseline (speedup 1.0000x reference)
#include <cuda_runtime.h>

// HierarchicalSoftmax: out[b, c*320 + t] = top[b,c] + bottom[b,t]
// B=1024, NHID=128, NCLASSES=320, PER_CLASS=320, out=[1024,102400] f32 (419 MB).
//
// Two-phase: (A) tiny dual GEMM -> __device__ scratch, (B) pure broadcast-add
// stream with register-cached bottom values (period-5 index cycle) and
// streaming stores.

#define BATCH      1024
#define NHID       128
#define NCLASSES   320
#define PER_CLASS  320
#define ROW_OUT    (NCLASSES * PER_CLASS)   // 102400
#define SEGS       8
#define CLS_PER_SEG (NCLASSES / SEGS)       // 40
#define F4_PER_SEG (CLS_PER_SEG * PER_CLASS / 4)  // 3200
#define TB         128                      // stream-kernel threads

__device__ float g_top[BATCH * NCLASSES];
__device__ float g_bot[BATCH * PER_CLASS];

// ---------------- Kernel A: compute top & bottom logits ----------------
__global__ __launch_bounds__(256) void hs_compute(
    const float* __restrict__ in,     // [1024, 128]
    const float* __restrict__ Wtop,   // [128, 320]
    const float* __restrict__ btop,   // [320]
    const float* __restrict__ Wbot,   // [320, 128]
    const float* __restrict__ bbot)   // [320]
{
    __shared__ float in_s[NHID];
    const int b   = blockIdx.x;
    const int tid = threadIdx.x;

    if (tid < NHID / 4) {
        reinterpret_cast<float4*>(in_s)[tid] =
            reinterpret_cast<const float4*>(in + (size_t)b * NHID)[tid];
    }
    __syncthreads();

    for (int j = tid; j < NCLASSES + PER_CLASS; j += 256) {
        if (j < NCLASSES) {
            float s = btop[j];
            const float* w = Wtop + j;   // column j, stride NCLASSES (coalesced over j)
            #pragma unroll 8
            for (int k = 0; k < NHID; k++)
                s = fmaf(in_s[k], w[k * NCLASSES], s);
            g_top[b * NCLASSES + j] = s;
        } else {
            const int t = j - NCLASSES;
            float s = bbot[t];
            const float4* w4 = reinterpret_cast<const float4*>(Wbot + (size_t)t * NHID);
            #pragma unroll 8
            for (int k = 0; k < NHID / 4; k++) {
                float4 w = w4[k];
                s = fmaf(in_s[4 * k + 0], w.x, s);
                s = fmaf(in_s[4 * k + 1], w.y, s);
                s = fmaf(in_s[4 * k + 2], w.z, s);
                s = fmaf(in_s[4 * k + 3], w.w, s);
            }
            g_bot[b * PER_CLASS + t] = s;
        }
    }
}

// ---------------- Kernel B: broadcast-add output stream ----------------
// Each CTA handles one (row, segment): 40 classes x 320 = 12800 floats = 3200 f4.
// With TB=128 threads: i = tid + 128*k, k=0..24.  gcd(128,80)=16 =>
// i mod 80 cycles through 5 fixed values (period 5) -> preload 5 float4 regs.
// i/80 advances by exactly 8 every 5 iterations -> no divides in the loop.
__global__ __launch_bounds__(TB) void hs_stream(float* __restrict__ out)
{
    __shared__ float  top_s[CLS_PER_SEG];
    __shared__ float4 bot_s[PER_CLASS / 4];   // 80 float4

    const int b   = blockIdx.x >> 3;
    const int seg = blockIdx.x & 7;
    const int tid = threadIdx.x;

    if (tid < 80) {
        bot_s[tid] = reinterpret_cast<const float4*>(g_bot + b * PER_CLASS)[tid];
    } else if (tid < 80 + CLS_PER_SEG) {
        top_s[tid - 80] = g_top[b * NCLASSES + seg * CLS_PER_SEG + (tid - 80)];
    }
    __syncthreads();

    // Preload the 5-periodic bottom values and class offsets.
    float4 bv[5];
    int    cm[5];
    #pragma unroll
    for (int m = 0; m < 5; m++) {
        const int i = tid + TB * m;
        bv[m] = bot_s[i % 80];   // compile-time-known modulus; computed once
        cm[m] = i / 80;          // 0..7
    }

    float4* __restrict__ out4 =
        reinterpret_cast<float4*>(out + (size_t)b * ROW_OUT) + seg * F4_PER_SEG;

    #pragma unroll
    for (int p = 0; p < 5; p++) {          // every 5 iters the class advances by 8
        #pragma unroll
        for (int m = 0; m < 5; m++) {
            const float tv = top_s[cm[m] + 8 * p];   // broadcast LDS (<=2 vals/warp)
            float4 v = bv[m];
            v.x += tv; v.y += tv; v.z += tv; v.w += tv;
            __stcs(out4 + p * (5 * TB) + m * TB + tid, v);  // streaming store
        }
    }
}

extern "C" void kernel_launch(void* const* d_in, const int* in_sizes, int n_in,
                              void* d_out, int out_size) {
    const float* in   = (const float*)d_in[0];
    const float* Wtop = (const float*)d_in[1];
    const float* btop = (const float*)d_in[2];
    const float* Wbot = (const float*)d_in[3];
    const float* bbot = (const float*)d_in[4];
    float* out = (float*)d_out;

    hs_compute<<<BATCH, 256>>>(in, Wtop, btop, Wbot, bbot);
    hs_stream<<<BATCH * SEGS, TB>>>(out);
}

// round 3
// speedup vs baseline: 1.8736x; 1.8736x over previous
#include <cuda_runtime.h>

// HierarchicalSoftmax: out[b, c*320 + t] = top[b,c] + bottom[b,t]
// Phase A: tiled GEMM [1024x128]@[128x640] -> g_top/g_bot   (~5 us)
// Phase B: broadcast-add output stream, 419 MB stores       (~65 us)

#define BATCH      1024
#define NHID       128
#define NCLASSES   320
#define PER_CLASS  320
#define ROW_OUT    (NCLASSES * PER_CLASS)   // 102400
#define SEGS       8
#define CLS_PER_SEG (NCLASSES / SEGS)       // 40
#define F4_PER_SEG (CLS_PER_SEG * PER_CLASS / 4)  // 3200
#define TB         128

// GEMM tiling
#define BM 64
#define BN 32
#define ASTR 130   // A smem row stride (pad: 4-apart rows hit distinct banks)
#define BSTR 129   // B smem row stride (pad: 4-apart cols hit distinct banks)

__device__ float g_top[BATCH * NCLASSES];
__device__ float g_bot[BATCH * PER_CLASS];

// ---------------- Kernel A: tiled dual GEMM ----------------
// Output column space j in [0,640): j<320 -> top (Wtop k-major [128,320]),
// j>=320 -> bottom (Wbot row-major [320,128]). BN=32 divides 320 so every
// CTA column-tile is purely top or purely bottom.
__global__ __launch_bounds__(128) void hs_gemm(
    const float* __restrict__ in,     // [1024, 128]
    const float* __restrict__ Wtop,   // [128, 320]
    const float* __restrict__ btop,   // [320]
    const float* __restrict__ Wbot,   // [320, 128]
    const float* __restrict__ bbot)   // [320]
{
    __shared__ float A[BM * ASTR];    // input rows   [64][130]
    __shared__ float B[BN * BSTR];    // weight cols  [32][129] (k-contiguous)

    const int bm  = blockIdx.x;           // 0..15  batch tile
    const int bn  = blockIdx.y;           // 0..19  col tile
    const int tid = threadIdx.x;
    const bool is_top = (bn < NCLASSES / BN);   // bn<10
    const int  jbase  = bn * BN;                // global col of tile (0..608)

    // Load A tile: 64 rows x 128, float4 global reads -> scalar STS (padded).
    {
        const float4* src = reinterpret_cast<const float4*>(in + (size_t)bm * BM * NHID);
        #pragma unroll
        for (int it = 0; it < (BM * NHID / 4) / 128; it++) {
            const int idx = tid + it * 128;
            const int row = idx >> 5;          // /32 f4 per row
            const int k4  = idx & 31;
            float4 v = src[idx];
            float* dst = A + row * ASTR + k4 * 4;
            dst[0] = v.x; dst[1] = v.y; dst[2] = v.z; dst[3] = v.w;
        }
    }

    // Load B tile: 32 cols x 128 k-values.
    if (is_top) {
        // B[jj][k] = Wtop[k*320 + jbase+jj]; iterate (k, jj) coalesced over jj.
        #pragma unroll
        for (int it = 0; it < (BN * NHID) / 128; it++) {
            const int idx = tid + it * 128;
            const int k  = idx >> 5;           // /32
            const int jj = idx & 31;
            B[jj * BSTR + k] = Wtop[k * NCLASSES + jbase + jj];
        }
    } else {
        // B[jj][k] = Wbot[(jbase-320+jj)*128 + k]; float4 over k.
        const float4* src = reinterpret_cast<const float4*>(
            Wbot + (size_t)(jbase - NCLASSES) * NHID);
        #pragma unroll
        for (int it = 0; it < (BN * NHID / 4) / 128; it++) {
            const int idx = tid + it * 128;
            const int jj = idx >> 5;
            const int k4 = idx & 31;
            float4 v = src[idx];
            float* dst = B + jj * BSTR + k4 * 4;
            dst[0] = v.x; dst[1] = v.y; dst[2] = v.z; dst[3] = v.w;
        }
    }
    __syncthreads();

    // Microtile: 16x8 thread grid, each thread 4 rows x 4 cols.
    const int tr = tid >> 3;     // 0..15 -> rows tr*4..+4
    const int tc = tid & 7;      // 0..7  -> cols tc*4..+4

    float acc[4][4];
    #pragma unroll
    for (int i = 0; i < 4; i++)
        #pragma unroll
        for (int j = 0; j < 4; j++) acc[i][j] = 0.0f;

    const float* Ap = A + tr * 4 * ASTR;
    const float* Bp = B + tc * 4 * BSTR;

    #pragma unroll 4
    for (int k = 0; k < NHID; k++) {
        float a0 = Ap[0 * ASTR + k], a1 = Ap[1 * ASTR + k];
        float a2 = Ap[2 * ASTR + k], a3 = Ap[3 * ASTR + k];
        float b0 = Bp[0 * BSTR + k], b1 = Bp[1 * BSTR + k];
        float b2 = Bp[2 * BSTR + k], b3 = Bp[3 * BSTR + k];
        acc[0][0] = fmaf(a0, b0, acc[0][0]); acc[0][1] = fmaf(a0, b1, acc[0][1]);
        acc[0][2] = fmaf(a0, b2, acc[0][2]); acc[0][3] = fmaf(a0, b3, acc[0][3]);
        acc[1][0] = fmaf(a1, b0, acc[1][0]); acc[1][1] = fmaf(a1, b1, acc[1][1]);
        acc[1][2] = fmaf(a1, b2, acc[1][2]); acc[1][3] = fmaf(a1, b3, acc[1][3]);
        acc[2][0] = fmaf(a2, b0, acc[2][0]); acc[2][1] = fmaf(a2, b1, acc[2][1]);
        acc[2][2] = fmaf(a2, b2, acc[2][2]); acc[2][3] = fmaf(a2, b3, acc[2][3]);
        acc[3][0] = fmaf(a3, b0, acc[3][0]); acc[3][1] = fmaf(a3, b1, acc[3][1]);
        acc[3][2] = fmaf(a3, b2, acc[3][2]); acc[3][3] = fmaf(a3, b3, acc[3][3]);
    }

    // Bias + writeback.
    const int row0 = bm * BM + tr * 4;
    #pragma unroll
    for (int j = 0; j < 4; j++) {
        const int jg = jbase + tc * 4 + j;
        const float bias = is_top ? btop[jg] : bbot[jg - NCLASSES];
        if (is_top) {
            #pragma unroll
            for (int i = 0; i < 4; i++)
                g_top[(size_t)(row0 + i) * NCLASSES + jg] = acc[i][j] + bias;
        } else {
            #pragma unroll
            for (int i = 0; i < 4; i++)
                g_bot[(size_t)(row0 + i) * PER_CLASS + (jg - NCLASSES)] = acc[i][j] + bias;
        }
    }
}

// ---------------- Kernel B: broadcast-add output stream ----------------
// (unchanged from R2 — 64.5 us @ 71% DRAM)
__global__ __launch_bounds__(TB) void hs_stream(float* __restrict__ out)
{
    __shared__ float  top_s[CLS_PER_SEG];
    __shared__ float4 bot_s[PER_CLASS / 4];

    const int b   = blockIdx.x >> 3;
    const int seg = blockIdx.x & 7;
    const int tid = threadIdx.x;

    if (tid < 80) {
        bot_s[tid] = reinterpret_cast<const float4*>(g_bot + b * PER_CLASS)[tid];
    } else if (tid < 80 + CLS_PER_SEG) {
        top_s[tid - 80] = g_top[b * NCLASSES + seg * CLS_PER_SEG + (tid - 80)];
    }
    __syncthreads();

    float4 bv[5];
    int    cm[5];
    #pragma unroll
    for (int m = 0; m < 5; m++) {
        const int i = tid + TB * m;
        bv[m] = bot_s[i % 80];
        cm[m] = i / 80;
    }

    float4* __restrict__ out4 =
        reinterpret_cast<float4*>(out + (size_t)b * ROW_OUT) + seg * F4_PER_SEG;

    #pragma unroll
    for (int p = 0; p < 5; p++) {
        #pragma unroll
        for (int m = 0; m < 5; m++) {
            const float tv = top_s[cm[m] + 8 * p];
            float4 v = bv[m];
            v.x += tv; v.y += tv; v.z += tv; v.w += tv;
            __stcs(out4 + p * (5 * TB) + m * TB + tid, v);
        }
    }
}

extern "C" void kernel_launch(void* const* d_in, const int* in_sizes, int n_in,
                              void* d_out, int out_size) {
    const float* in   = (const float*)d_in[0];
    const float* Wtop = (const float*)d_in[1];
    const float* btop = (const float*)d_in[2];
    const float* Wbot = (const float*)d_in[3];
    const float* bbot = (const float*)d_in[4];
    float* out = (float*)d_out;

    dim3 grid(BATCH / BM, (NCLASSES + PER_CLASS) / BN);   // 16 x 20
    hs_gemm<<<grid, 128>>>(in, Wtop, btop, Wbot, bbot);
    hs_stream<<<BATCH * SEGS, TB>>>(out);
}